// round 6
// baseline (speedup 1.0000x reference)
#include <cuda_runtime.h>
#include <cuda_fp16.h>
#include <cstdint>

// N=32768 tokens, D=128, K=1024 codes. scores = ||c||^2 - 2 x.c
// 3xFP16 split: dot ~= xh*ch (fp32 acc) + [xh*cl + xl*ch] (fp16 acc, 2x rate)
// 512 threads / 16 warps, 32x32 warp tiles.

#define NTOK     32768
#define DDIM     128
#define KCODES   1024
#define MT       128
#define NTILE    128
#define NT_CNT   (KCODES / NTILE)   // 8
#define NTHREADS 512

__device__ __half g_cbh[KCODES * DDIM];
__device__ __half g_cbl[KCODES * DDIM];
__device__ float  g_cnorm[KCODES];

// ---------------- SMEM layout (bytes) ----------------
#define SM_AH   0
#define SM_AL   32768
#define SM_B    65536
#define SM_RED  196608
#define SM_BEST 200704
#define SMEM_BYTES 201216

__device__ __forceinline__ uint32_t smem_u32(const void* p) {
    uint32_t a;
    asm("{ .reg .u64 t; cvta.to.shared.u64 t, %1; cvt.u32.u64 %0, t; }" : "=r"(a) : "l"(p));
    return a;
}
__device__ __forceinline__ void cp_async16(uint32_t dst, const void* src) {
    asm volatile("cp.async.cg.shared.global [%0], [%1], 16;" :: "r"(dst), "l"(src) : "memory");
}
__device__ __forceinline__ void cp_commit() {
    asm volatile("cp.async.commit_group;" ::: "memory");
}
template <int W>
__device__ __forceinline__ void cp_wait() {
    asm volatile("cp.async.wait_group %0;" :: "n"(W) : "memory");
}
__device__ __forceinline__ void ldsm4(uint32_t& r0, uint32_t& r1, uint32_t& r2, uint32_t& r3,
                                      uint32_t addr) {
    asm volatile("ldmatrix.sync.aligned.m8n8.x4.shared.b16 {%0,%1,%2,%3}, [%4];"
                 : "=r"(r0), "=r"(r1), "=r"(r2), "=r"(r3) : "r"(addr));
}
// fp32-accumulator HMMA
__device__ __forceinline__ void mma_f32(float* c, const uint32_t* a, uint32_t b0, uint32_t b1) {
    asm volatile(
        "mma.sync.aligned.m16n8k16.row.col.f32.f16.f16.f32 "
        "{%0,%1,%2,%3}, {%4,%5,%6,%7}, {%8,%9}, {%0,%1,%2,%3};"
        : "+f"(c[0]), "+f"(c[1]), "+f"(c[2]), "+f"(c[3])
        : "r"(a[0]), "r"(a[1]), "r"(a[2]), "r"(a[3]), "r"(b0), "r"(b1));
}
// fp16-accumulator HMMA (2 b32 regs = 4 halves)
__device__ __forceinline__ void mma_f16(uint32_t* c, const uint32_t* a, uint32_t b0, uint32_t b1) {
    asm volatile(
        "mma.sync.aligned.m16n8k16.row.col.f16.f16.f16.f16 "
        "{%0,%1}, {%2,%3,%4,%5}, {%6,%7}, {%0,%1};"
        : "+r"(c[0]), "+r"(c[1])
        : "r"(a[0]), "r"(a[1]), "r"(a[2]), "r"(a[3]), "r"(b0), "r"(b1));
}
__device__ __forceinline__ uint32_t fp_order(float f) {
    uint32_t u = __float_as_uint(f);
    return u ^ ((u >> 31) ? 0xFFFFFFFFu : 0x80000000u);
}

// ---------------- prep: fp16 split of codebook + norms ----------------
__global__ void prep_kernel(const float* __restrict__ cb) {
    int k = blockIdx.x, d = threadIdx.x;
    float v = cb[k * DDIM + d];
    __half h = __float2half_rn(v);
    g_cbh[k * DDIM + d] = h;
    g_cbl[k * DDIM + d] = __float2half_rn(v - __half2float(h));
    float s = v * v;
#pragma unroll
    for (int o = 16; o; o >>= 1) s += __shfl_xor_sync(~0u, s, o);
    __shared__ float ws[4];
    if ((threadIdx.x & 31) == 0) ws[threadIdx.x >> 5] = s;
    __syncthreads();
    if (threadIdx.x == 0) g_cnorm[k] = ws[0] + ws[1] + ws[2] + ws[3];
}

extern __shared__ char smem[];

__device__ __forceinline__ void issue_b_tile(uint32_t sb, int nt, int st, int tid) {
#pragma unroll
    for (int i = 0; i < 8; i++) {
        int ch   = i * NTHREADS + tid;          // 4096 chunks of 16B
        int comp = ch >> 11;                     // 0 hi, 1 lo
        int rem  = ch & 2047;
        int row  = rem >> 4;
        int c16  = rem & 15;
        const __half* src = (comp ? g_cbl : g_cbh) + ((size_t)(nt * NTILE + row) * DDIM + c16 * 8);
        uint32_t dst = sb + SM_B + (uint32_t)(st * 2 + comp) * 32768u
                     + (uint32_t)(row * 16 + (c16 ^ (row & 7))) * 16u;
        cp_async16(dst, src);
    }
    cp_commit();
}

__global__ __launch_bounds__(NTHREADS, 1) void vq_mma_kernel(
    const float* __restrict__ x, const float* __restrict__ cb, float* __restrict__ out)
{
    const uint32_t sb = smem_u32(smem);
    const int tid  = threadIdx.x;
    const int lane = tid & 31;
    const int warp = tid >> 5;
    const int wm   = warp >> 2;        // 0..3 : rows wm*32..+31
    const int wn   = warp & 3;         // 0..3 : cols wn*32..+31
    const int m0   = blockIdx.x * MT;

    unsigned long long* red = reinterpret_cast<unsigned long long*>(smem + SM_RED);
    int* smem_best = reinterpret_cast<int*>(smem + SM_BEST);

    // ---- prologue: stage x fp32 (contiguous tile), split to fp16 SMEM ----
    {
        const float4* xsrc = reinterpret_cast<const float4*>(x + (size_t)m0 * DDIM);
        float4* xstage = reinterpret_cast<float4*>(smem + SM_B);
#pragma unroll
        for (int i = 0; i < 8; i++) xstage[i * NTHREADS + tid] = xsrc[i * NTHREADS + tid];
        __syncthreads();
        const float* xs = reinterpret_cast<const float*>(smem + SM_B);
#pragma unroll
        for (int i = 0; i < 4; i++) {
            int oc  = i * NTHREADS + tid;       // 2048 fp16 chunks (16B = 8 halfs)
            int row = oc >> 4;
            int hc  = oc & 15;
            const float* p = xs + row * DDIM + hc * 8;
            uint32_t hi[4], lo[4];
#pragma unroll
            for (int j = 0; j < 4; j++) {
                float v0 = p[j * 2], v1 = p[j * 2 + 1];
                __half h0 = __float2half_rn(v0), h1 = __float2half_rn(v1);
                __half l0 = __float2half_rn(v0 - __half2float(h0));
                __half l1 = __float2half_rn(v1 - __half2float(h1));
                hi[j] = ((uint32_t)__half_as_ushort(h1) << 16) | __half_as_ushort(h0);
                lo[j] = ((uint32_t)__half_as_ushort(l1) << 16) | __half_as_ushort(l0);
            }
            uint32_t chunk = (uint32_t)(row * 16 + (hc ^ (row & 7))) * 16u;
            *reinterpret_cast<uint4*>(smem + SM_AH + chunk) = make_uint4(hi[0], hi[1], hi[2], hi[3]);
            *reinterpret_cast<uint4*>(smem + SM_AL + chunk) = make_uint4(lo[0], lo[1], lo[2], lo[3]);
        }
        __syncthreads();   // x-stage (B region) free for prefetch
    }

    issue_b_tile(sb, 0, 0, tid);
    issue_b_tile(sb, 1, 1, tid);

    unsigned long long bestp[4];
#pragma unroll
    for (int i = 0; i < 4; i++) bestp[i] = ~0ull;

    const int t8 = lane >> 3;     // ldmatrix sub-tile select
    const int j8 = lane & 7;      // ldmatrix row-in-tile

    for (int nt = 0; nt < NT_CNT; nt++) {
        if (nt + 1 < NT_CNT) cp_wait<1>(); else cp_wait<0>();
        __syncthreads();
        const int st = nt & 1;
        const uint32_t bhb = sb + SM_B + (uint32_t)(st * 2) * 32768u;
        const uint32_t blb = bhb + 32768u;

        float    accf[2][4][4];     // xh*ch, fp32 accumulation
        uint32_t acch[2][4][2];     // xh*cl + xl*ch, fp16 accumulation (4 halves)
#pragma unroll
        for (int mi = 0; mi < 2; mi++)
#pragma unroll
            for (int ni = 0; ni < 4; ni++) {
#pragma unroll
                for (int c = 0; c < 4; c++) accf[mi][ni][c] = 0.f;
                acch[mi][ni][0] = 0u; acch[mi][ni][1] = 0u;
            }

#pragma unroll
        for (int kc = 0; kc < 8; kc++) {
            const int c16 = kc * 2 + (t8 >> 1);
            uint32_t ah[2][4], al[2][4];
#pragma unroll
            for (int mi = 0; mi < 2; mi++) {
                int row = wm * 32 + mi * 16 + (t8 & 1) * 8 + j8;
                uint32_t off = (uint32_t)(row * 16 + (c16 ^ (row & 7))) * 16u;
                ldsm4(ah[mi][0], ah[mi][1], ah[mi][2], ah[mi][3], sb + SM_AH + off);
                ldsm4(al[mi][0], al[mi][1], al[mi][2], al[mi][3], sb + SM_AL + off);
            }
            uint32_t bh[2][4], bl[2][4];
#pragma unroll
            for (int bi = 0; bi < 2; bi++) {
                int nrow = wn * 32 + bi * 16 + (t8 & 1) * 8 + j8;
                uint32_t off = (uint32_t)(nrow * 16 + (c16 ^ (nrow & 7))) * 16u;
                ldsm4(bh[bi][0], bh[bi][1], bh[bi][2], bh[bi][3], bhb + off);
                ldsm4(bl[bi][0], bl[bi][1], bl[bi][2], bl[bi][3], blb + off);
            }
#pragma unroll
            for (int mi = 0; mi < 2; mi++)
#pragma unroll
                for (int ni = 0; ni < 4; ni++) {
                    int bi = ni >> 1, sub = ni & 1;
                    mma_f32(accf[mi][ni], ah[mi], bh[bi][sub], bh[bi][sub + 2]);
                    mma_f16(acch[mi][ni], ah[mi], bl[bi][sub], bl[bi][sub + 2]);
                    mma_f16(acch[mi][ni], al[mi], bh[bi][sub], bh[bi][sub + 2]);
                }
        }

        // ---- fold scores into per-lane argmin ----
#pragma unroll
        for (int ni = 0; ni < 4; ni++) {
            int col0 = nt * NTILE + wn * 32 + ni * 8 + 2 * (lane & 3);
            float cn0 = __ldg(&g_cnorm[col0]);
            float cn1 = __ldg(&g_cnorm[col0 + 1]);
#pragma unroll
            for (int mi = 0; mi < 2; mi++) {
                float2 c01 = __half22float2(*reinterpret_cast<__half2*>(&acch[mi][ni][0]));
                float2 c23 = __half22float2(*reinterpret_cast<__half2*>(&acch[mi][ni][1]));
                float s00 = fmaf(-2.f, accf[mi][ni][0] + c01.x, cn0);
                float s01 = fmaf(-2.f, accf[mi][ni][1] + c01.y, cn1);
                float s10 = fmaf(-2.f, accf[mi][ni][2] + c23.x, cn0);
                float s11 = fmaf(-2.f, accf[mi][ni][3] + c23.y, cn1);
                unsigned long long p00 = ((unsigned long long)fp_order(s00) << 32) | (uint32_t)col0;
                unsigned long long p01 = ((unsigned long long)fp_order(s01) << 32) | (uint32_t)(col0 + 1);
                unsigned long long p10 = ((unsigned long long)fp_order(s10) << 32) | (uint32_t)col0;
                unsigned long long p11 = ((unsigned long long)fp_order(s11) << 32) | (uint32_t)(col0 + 1);
                int rlo = mi * 2, rhi = mi * 2 + 1;
                if (p00 < bestp[rlo]) bestp[rlo] = p00;
                if (p01 < bestp[rlo]) bestp[rlo] = p01;
                if (p10 < bestp[rhi]) bestp[rhi] = p10;
                if (p11 < bestp[rhi]) bestp[rhi] = p11;
            }
        }

        __syncthreads();   // all warps done with stage st before overwrite
        if (nt + 2 < NT_CNT) issue_b_tile(sb, nt + 2, st, tid);
    }

    // ---- cross-lane reduce (within quad: lanes sharing rows) ----
#pragma unroll
    for (int i = 0; i < 4; i++) {
        unsigned long long p = bestp[i];
        unsigned long long q;
        q = __shfl_xor_sync(~0u, p, 1); if (q < p) p = q;
        q = __shfl_xor_sync(~0u, p, 2); if (q < p) p = q;
        bestp[i] = p;
    }
    if ((lane & 3) == 0) {
#pragma unroll
        for (int mi = 0; mi < 2; mi++)
#pragma unroll
            for (int h = 0; h < 2; h++) {
                int row = wm * 32 + mi * 16 + h * 8 + (lane >> 2);
                red[row * 4 + wn] = bestp[mi * 2 + h];
            }
    }
    __syncthreads();
    if (tid < MT) {
        unsigned long long p = red[tid * 4];
#pragma unroll
        for (int w = 1; w < 4; w++) {
            unsigned long long q = red[tid * 4 + w];
            if (q < p) p = q;
        }
        smem_best[tid] = (int)(p & 0xFFFFFFFFu);
    }
    __syncthreads();

    // ---- output: out = x + (q - x), coalesced float4 ----
    const float4* x4  = reinterpret_cast<const float4*>(x);
    const float4* cb4 = reinterpret_cast<const float4*>(cb);
    float4* o4 = reinterpret_cast<float4*>(out);
#pragma unroll
    for (int i = 0; i < 8; i++) {
        int g  = i * NTHREADS + tid;            // 4096 float4
        int r  = g >> 5, c4 = g & 31;
        int bi = smem_best[r];
        float4 xv = x4[(size_t)(m0 + r) * 32 + c4];
        float4 qv = cb4[(size_t)bi * 32 + c4];
        float4 ov;
        ov.x = xv.x + (qv.x - xv.x);
        ov.y = xv.y + (qv.y - xv.y);
        ov.z = xv.z + (qv.z - xv.z);
        ov.w = xv.w + (qv.w - xv.w);
        o4[(size_t)(m0 + r) * 32 + c4] = ov;
    }
}

extern "C" void kernel_launch(void* const* d_in, const int* in_sizes, int n_in,
                              void* d_out, int out_size) {
    const float* x  = (const float*)d_in[0];
    const float* cb = (const float*)d_in[1];
    float* out = (float*)d_out;
    int N = in_sizes[0] / DDIM;     // 32768
    int K = in_sizes[1] / DDIM;     // 1024

    prep_kernel<<<K, DDIM>>>(cb);

    cudaFuncSetAttribute(vq_mma_kernel, cudaFuncAttributeMaxDynamicSharedMemorySize, SMEM_BYTES);
    vq_mma_kernel<<<N / MT, NTHREADS, SMEM_BYTES>>>(x, cb, out);
}